// round 13
// baseline (speedup 1.0000x reference)
#include <cuda_runtime.h>
#include <math.h>
#include <stdint.h>

#define BB 2
#define NN 160
#define HH 256
#define C3 768
#define FF 512
#define NP (NN*NN)            // 25600
#define MM (BB*NN)            // 320
#define LOGIT_ELEMS (BB*NP*2) // 102400 per head
#define EMB_OFF (3*LOGIT_ELEMS)

// PQ scratch: [h = t*2+s][m][f]
__device__ float g_PQ[3 * 2 * MM * FF];

#define FFMA2(acc, a, b) asm("fma.rn.f32x2 %0, %1, %2, %0;" : "+l"(acc) : "l"(a), "l"(b))
#define PACKDUP(d, x)    asm("mov.b64 %0, {%1, %1};" : "=l"(d) : "r"(__float_as_uint(x)))
#define UNPK(lo, hi, v)  asm("mov.b64 {%0, %1}, %2;" : "=r"(lo), "=r"(hi) : "l"(v))

#define BM 64
#define BN 64
#define BK 16
#define NK 48
#define AST 68
#define GEMM_BLOCKS 240
#define JT 10
#define WR_TILES 5120
#define LG_BLOCKS 150

#define SMEM_BYTES 33824   // writer 33800 / logits 33792 union

// ---------------- Kernel A: GEMM standalone (sync double-buffer) ----------------
__global__ __launch_bounds__(256) void k_gemm(
    const float* __restrict__ geo, const float* __restrict__ app, const float* __restrict__ con,
    const float* __restrict__ W1c, const float* __restrict__ b1c,
    const float* __restrict__ W1r, const float* __restrict__ b1r,
    const float* __restrict__ W1l, const float* __restrict__ b1l)
{
    __shared__ float As[2][BK*AST];
    __shared__ float Bs[2][BK*BN];
    const int g = blockIdx.x;
    const int tid = threadIdx.x;

    const int nt = g % 48;
    const int mt = g / 48;
    const int t  = nt >> 4;
    const int s  = (nt >> 3) & 1;
    const int f0 = (nt & 7) * BN;
    const float* W1 = (t==0 ? W1c : (t==1 ? W1r : W1l)) + (size_t)s * C3 * FF;
    const float* b1 = (t==0 ? b1c : (t==1 ? b1r : b1l));
    const int m0 = mt * BM;

    const int arow = tid >> 2, av = tid & 3;
    const int kr = tid >> 4, fo = (tid & 15) * 4;
    const int rg = tid >> 4, cg = tid & 15;

    unsigned long long acc2[4][2];
    #pragma unroll
    for (int a = 0; a < 4; a++) { acc2[a][0] = 0ull; acc2[a][1] = 0ull; }

    float4 pa, pb;
    pa = *(const float4*)(geo + (size_t)(m0 + arow) * HH + av * 4);
    pb = *(const float4*)(W1 + (size_t)kr * FF + f0 + fo);
    As[0][(av*4+0)*AST + arow] = pa.x;
    As[0][(av*4+1)*AST + arow] = pa.y;
    As[0][(av*4+2)*AST + arow] = pa.z;
    As[0][(av*4+3)*AST + arow] = pa.w;
    *(float4*)&Bs[0][kr*BN + fo] = pb;
    __syncthreads();

    for (int kt = 0; kt < NK; kt++) {
        const int cur = kt & 1;
        const int nxt = cur ^ 1;
        if (kt + 1 < NK) {
            const int c0 = (kt + 1) * BK;
            const float* segp = (c0 < 256) ? geo : ((c0 < 512) ? app : con);
            pa = *(const float4*)(segp + (size_t)(m0 + arow) * HH + (c0 & 255) + av * 4);
            pb = *(const float4*)(W1 + (size_t)(c0 + kr) * FF + f0 + fo);
        }
        #pragma unroll
        for (int k = 0; k < BK; k++) {
            const float4 a4 = *(const float4*)&As[cur][k*AST + rg*4];
            const ulonglong2 b2v = *(const ulonglong2*)&Bs[cur][k*BN + cg*4];
            float avv[4] = {a4.x, a4.y, a4.z, a4.w};
            #pragma unroll
            for (int a = 0; a < 4; a++) {
                unsigned long long ad;
                PACKDUP(ad, avv[a]);
                FFMA2(acc2[a][0], ad, b2v.x);
                FFMA2(acc2[a][1], ad, b2v.y);
            }
        }
        if (kt + 1 < NK) {
            __syncthreads();
            As[nxt][(av*4+0)*AST + arow] = pa.x;
            As[nxt][(av*4+1)*AST + arow] = pa.y;
            As[nxt][(av*4+2)*AST + arow] = pa.z;
            As[nxt][(av*4+3)*AST + arow] = pa.w;
            *(float4*)&Bs[nxt][kr*BN + fo] = pb;
            __syncthreads();
        }
    }

    float bv[4] = {0.f, 0.f, 0.f, 0.f};
    if (s == 1) {
        const float4 tb = *(const float4*)(b1 + f0 + cg*4);
        bv[0]=tb.x; bv[1]=tb.y; bv[2]=tb.z; bv[3]=tb.w;
    }
    const size_t hb = (size_t)(t*2 + s) * MM * FF;
    #pragma unroll
    for (int a = 0; a < 4; a++) {
        const int m = m0 + rg*4 + a;
        unsigned int lo0, hi0, lo1, hi1;
        UNPK(lo0, hi0, acc2[a][0]);
        UNPK(lo1, hi1, acc2[a][1]);
        *(float4*)(g_PQ + hb + (size_t)m * FF + f0 + cg*4) =
            make_float4(__uint_as_float(lo0) + bv[0], __uint_as_float(hi0) + bv[1],
                        __uint_as_float(lo1) + bv[2], __uint_as_float(hi1) + bv[3]);
    }
}

// ---------------- writer role: TMA bulk pipeline ----------------
// wb in [0, 5120): b = wb/2560, i = (wb%2560)/16, j0 = ((wb%2560)%16)*10
__device__ __forceinline__ void writer_role(
    int wb,
    const float* __restrict__ geo, const float* __restrict__ app, const float* __restrict__ con,
    float* __restrict__ out, int tid, char* sm)
{
    const int b  = wb / 2560;
    const int rem = wb % 2560;
    const int i  = rem / 16;
    const int j0 = (rem % 16) * JT;

    const uint32_t sbase = (uint32_t)__cvta_generic_to_shared(sm);
    const uint32_t mbar  = sbase + 11 * 3072;

    if (tid == 0) {
        asm volatile("mbarrier.init.shared.b64 [%0], 1;" :: "r"(mbar) : "memory");
    }
    __syncthreads();
    if (tid == 0) {
        asm volatile("mbarrier.arrive.expect_tx.shared.b64 _, [%0], %1;"
                     :: "r"(mbar), "r"(11u * 3072u) : "memory");
    }
    __syncthreads();

    if (tid < 33) {
        const int r = tid / 3, seg = tid - 3 * (tid / 3);
        const int n = (r < JT) ? (j0 + r) : i;
        const float* src = ((seg == 0) ? geo : (seg == 1) ? app : con)
                           + ((size_t)b * NN + n) * HH;
        asm volatile(
            "cp.async.bulk.shared::cluster.global.mbarrier::complete_tx::bytes "
            "[%0], [%1], %2, [%3];"
            :: "r"(sbase + (uint32_t)(r * 3072 + seg * 1024)), "l"(src),
               "r"(1024u), "r"(mbar) : "memory");
    }

    if (tid < 2 * JT) {
        asm volatile(
            "{\n\t.reg .pred P;\n"
            "W%=:\n\t"
            "mbarrier.try_wait.parity.shared.b64 P, [%0], 0, 0x989680;\n\t"
            "@!P bra W%=;\n\t}"
            :: "r"(mbar) : "memory");

        const int jj = tid >> 1, half = tid & 1;
        const size_t pidx = (size_t)b * NP + (size_t)i * NN + (j0 + jj);
        float* dst = out + EMB_OFF + pidx * 1536 + half * 768;
        const uint32_t src = sbase + (uint32_t)((half ? JT : jj) * 3072);
        asm volatile(
            "cp.async.bulk.global.shared::cta.bulk_group [%0], [%1], %2;"
            :: "l"(dst), "r"(src), "r"(3072u) : "memory");
        asm volatile("cp.async.bulk.commit_group;" ::: "memory");
        asm volatile("cp.async.bulk.wait_group 0;" ::: "memory");
    }
    __syncthreads();
}

// ---------------- Kernel B: logits (150) + writer (all 5120 tiles) ----------------
__global__ __launch_bounds__(256) void kB_lg_wr(
    const float* __restrict__ geo, const float* __restrict__ app, const float* __restrict__ con,
    float* __restrict__ out,
    const float* __restrict__ W2c, const float* __restrict__ b2c,
    const float* __restrict__ W2r, const float* __restrict__ b2r,
    const float* __restrict__ W2l, const float* __restrict__ b2l)
{
    __shared__ __align__(128) char sm[SMEM_BYTES];
    const int g = blockIdx.x;
    const int tid = threadIdx.x;

    if (g < LG_BLOCKS) {
        float* sP = (float*)sm;            // 32*132
        float* sQ = sP + 32*132;           // 32*128
        float* sW = sQ + 32*128;           // 128
        const int t = g / 50;
        const int r50 = g % 50;
        const int b = r50 / 25;
        const int r25 = r50 % 25;
        const int i0 = (r25 / 5) * 32;
        const int j0 = (r25 % 5) * 32;
        const float* W2 = (t==0 ? W2c : (t==1 ? W2r : W2l));
        const float* b2 = (t==0 ? b2c : (t==1 ? b2r : b2l));
        const size_t boff = (size_t)b * NN * FF;
        const float* Pb = g_PQ + (size_t)(t*2 + 0) * MM * FF + boff;
        const float* Qb = g_PQ + (size_t)(t*2 + 1) * MM * FF + boff;
        const int il = tid >> 5, jl = tid & 31;
        const int lr = tid >> 3, lv = tid & 7;

        float acc[4] = {0.f, 0.f, 0.f, 0.f};
        for (int fc = 0; fc < 4; fc++) {
            const int f0 = fc * 128;
            {
                const size_t ro = (size_t)(j0 + lr) * FF + f0;
                float* dp = sP + lr * 132;
                #pragma unroll
                for (int u = 0; u < 4; u++) {
                    const int fl = (lv + u * 8) * 4;
                    *(float4*)(dp + fl) = *(const float4*)(Pb + ro + fl);
                }
            }
            {
                const size_t ro = (size_t)(i0 + lr) * FF + f0;
                float* dp = sQ + lr * 128;
                #pragma unroll
                for (int u = 0; u < 4; u++) {
                    const int fl = (lv + u * 8) * 4;
                    *(float4*)(dp + fl) = *(const float4*)(Qb + ro + fl);
                }
            }
            if (tid < 128) {
                const float2 w2v = ((const float2*)W2)[f0 + tid];
                sW[tid] = w2v.x - w2v.y;
            }
            __syncthreads();

            const float* pr = sP + jl * 132;
            const float* q0 = sQ + (il * 4) * 128;
            #pragma unroll 4
            for (int f = 0; f < 128; f += 4) {
                const float4 p = *(const float4*)(pr + f);
                const float4 w = *(const float4*)(sW + f);
                #pragma unroll
                for (int a = 0; a < 4; a++) {
                    const float4 q = *(const float4*)(q0 + a * 128 + f);
                    acc[a] = fmaf(fmaxf(p.x + q.x, 0.f), w.x, acc[a]);
                    acc[a] = fmaf(fmaxf(p.y + q.y, 0.f), w.y, acc[a]);
                    acc[a] = fmaf(fmaxf(p.z + q.z, 0.f), w.z, acc[a]);
                    acc[a] = fmaf(fmaxf(p.w + q.w, 0.f), w.w, acc[a]);
                }
            }
            __syncthreads();
        }

        const float bd = b2[0] - b2[1];
        float2* o = (float2*)(out + (size_t)t * LOGIT_ELEMS) + (size_t)b * NP;
        const int j = j0 + jl;
        #pragma unroll
        for (int a = 0; a < 4; a++) {
            const float d = acc[a] + bd;
            const float p0 = 1.0f / (1.0f + __expf(-d));
            o[(size_t)(i0 + il*4 + a) * NN + j] = make_float2(p0, 1.0f - p0);
        }
    } else {
        writer_role(g - LG_BLOCKS, geo, app, con, out, tid, sm);
    }
}

extern "C" void kernel_launch(void* const* d_in, const int* in_sizes, int n_in,
                              void* d_out, int out_size) {
    const float* geo = (const float*)d_in[0];
    const float* app = (const float*)d_in[1];
    const float* con = (const float*)d_in[2];
    const float* W1c = (const float*)d_in[3];
    const float* b1c = (const float*)d_in[4];
    const float* W2c = (const float*)d_in[5];
    const float* b2c = (const float*)d_in[6];
    const float* W1r = (const float*)d_in[7];
    const float* b1r = (const float*)d_in[8];
    const float* W2r = (const float*)d_in[9];
    const float* b2r = (const float*)d_in[10];
    const float* W1l = (const float*)d_in[11];
    const float* b1l = (const float*)d_in[12];
    const float* W2l = (const float*)d_in[13];
    const float* b2l = (const float*)d_in[14];
    float* out = (float*)d_out;

    k_gemm<<<GEMM_BLOCKS, 256>>>(geo, app, con,
                                 W1c, b1c, W1r, b1r, W1l, b1l);
    kB_lg_wr<<<LG_BLOCKS + WR_TILES, 256>>>(geo, app, con, out,
                                            W2c, b2c, W2r, b2r, W2l, b2l);
}

// round 14
// speedup vs baseline: 1.1196x; 1.1196x over previous
#include <cuda_runtime.h>
#include <math.h>
#include <stdint.h>

#define BB 2
#define NN 160
#define HH 256
#define C3 768
#define FF 512
#define NP (NN*NN)            // 25600
#define MM (BB*NN)            // 320
#define KP 384                // C3/2
#define LOGIT_ELEMS (BB*NP*2) // 102400 per head
#define EMB_OFF (3*LOGIT_ELEMS)

// PQ scratch: [h = t*2+s][m][f]
__device__ float    g_PQ[6 * MM * FF];
// bf16x2 hi/lo packed operands: word(kp, x) = {lo=bf16(v[2kp]), hi=bf16(v[2kp+1])}
__device__ uint32_t g_Wp_hi[6 * KP * FF];
__device__ uint32_t g_Wp_lo[6 * KP * FF];
__device__ uint32_t g_Ep_hi[MM * KP];
__device__ uint32_t g_Ep_lo[MM * KP];

#define CPA16(dst, src)  asm volatile("cp.async.ca.shared.global [%0], [%1], 16;" :: "r"(dst), "l"(src) : "memory")
#define CPCOMMIT()       asm volatile("cp.async.commit_group;" ::: "memory")

__device__ __forceinline__ uint32_t pack2(float e, float o) {
    uint32_t w;  // lower half = e, upper half = o
    asm("cvt.rn.bf16x2.f32 %0, %1, %2;" : "=r"(w) : "f"(o), "f"(e));
    return w;
}

// ---------------- pre-convert: W1 + emb -> bf16x2 hi/lo ----------------
#define PRE_W_THREADS 294912   // 6 * 384 * 128 (4 f-words each)
#define PRE_E_THREADS 30720    // 320 * 96     (4 kp-words each)
#define PRE_BLOCKS 1272        // (294912+30720)/256

__global__ __launch_bounds__(256) void k_pre(
    const float* __restrict__ geo, const float* __restrict__ app, const float* __restrict__ con,
    const float* __restrict__ W1c, const float* __restrict__ W1r, const float* __restrict__ W1l)
{
    const int gt = blockIdx.x * 256 + threadIdx.x;
    if (gt < PRE_W_THREADS) {
        const int h  = gt / 49152;
        const int r  = gt % 49152;
        const int kp = r / 128;
        const int f4 = (r % 128) * 4;
        const float* Wb = (h < 2 ? W1c : (h < 4 ? W1r : W1l)) + (size_t)(h & 1) * C3 * FF;
        const float4 x0 = *(const float4*)(Wb + (size_t)(2*kp)   * FF + f4);
        const float4 x1 = *(const float4*)(Wb + (size_t)(2*kp+1) * FF + f4);
        const float e[4] = {x0.x, x0.y, x0.z, x0.w};
        const float o[4] = {x1.x, x1.y, x1.z, x1.w};
        uint32_t hi[4], lo[4];
        #pragma unroll
        for (int i = 0; i < 4; i++) {
            hi[i] = pack2(e[i], o[i]);
            const float ef = e[i] - __uint_as_float(hi[i] << 16);
            const float of = o[i] - __uint_as_float(hi[i] & 0xFFFF0000u);
            lo[i] = pack2(ef, of);
        }
        const size_t w = (size_t)(h * KP + kp) * FF + f4;
        *(uint4*)(g_Wp_hi + w) = make_uint4(hi[0], hi[1], hi[2], hi[3]);
        *(uint4*)(g_Wp_lo + w) = make_uint4(lo[0], lo[1], lo[2], lo[3]);
    } else {
        const int idx = gt - PRE_W_THREADS;   // < 30720
        const int m  = idx / 96;
        const int kg = idx % 96;
        const int k0 = kg * 8;
        const float* base = ((k0 < 256) ? geo : (k0 < 512) ? app : con)
                            + (size_t)m * HH + (k0 & 255);
        const float4 y0 = *(const float4*)(base);
        const float4 y1 = *(const float4*)(base + 4);
        const float v[8] = {y0.x, y0.y, y0.z, y0.w, y1.x, y1.y, y1.z, y1.w};
        uint32_t hi[4], lo[4];
        #pragma unroll
        for (int i = 0; i < 4; i++) {
            const float e = v[2*i], o = v[2*i+1];
            hi[i] = pack2(e, o);
            const float ef = e - __uint_as_float(hi[i] << 16);
            const float of = o - __uint_as_float(hi[i] & 0xFFFF0000u);
            lo[i] = pack2(ef, of);
        }
        const size_t w = (size_t)m * KP + kg * 4;
        *(uint4*)(g_Ep_hi + w) = make_uint4(hi[0], hi[1], hi[2], hi[3]);
        *(uint4*)(g_Ep_lo + w) = make_uint4(lo[0], lo[1], lo[2], lo[3]);
    }
}

// ---------------- GEMM: bf16 3-pass mma.sync, 4-stage cp.async ----------------
#define NKT 48           // k16 tiles
#define STG_WORDS 2624   // per stage: Ahi 768 (64x12), Alo 768, Bhi 544 (8x68), Blo 544
#define GEMM_BLOCKS 240

#define MMA_BF16(d, a, b) \
    asm volatile("mma.sync.aligned.m16n8k16.row.col.f32.bf16.bf16.f32 " \
        "{%0,%1,%2,%3}, {%4,%5,%6,%7}, {%8,%9}, {%0,%1,%2,%3};" \
        : "+f"((d)[0]), "+f"((d)[1]), "+f"((d)[2]), "+f"((d)[3]) \
        : "r"((a)[0]), "r"((a)[1]), "r"((a)[2]), "r"((a)[3]), "r"((b)[0]), "r"((b)[1]))

__global__ __launch_bounds__(256) void k_gemm_mma(
    const float* __restrict__ b1c, const float* __restrict__ b1r, const float* __restrict__ b1l)
{
    __shared__ __align__(16) uint32_t smw[4 * STG_WORDS];
    const int tid = threadIdx.x;
    const int gb = blockIdx.x;
    const int nt = gb % 48;
    const int m0 = (gb / 48) * 64;
    const int t  = nt >> 4;
    const int s  = (nt >> 3) & 1;
    const int f0 = (nt & 7) * 64;
    const int h  = t * 2 + s;
    const float* b1 = (t == 0 ? b1c : (t == 1 ? b1r : b1l));

    const uint32_t smbase = (uint32_t)__cvta_generic_to_shared(smw);
    // cp.async mappings (1 A-chunk + 1 B-chunk per thread per stage)
    const int arow = tid >> 2, ahl = (tid >> 1) & 1, ach = tid & 1;
    const uint32_t* srcA = (ahl ? g_Ep_lo : g_Ep_hi) + (size_t)(m0 + arow) * KP + ach * 4;
    const uint32_t dstA = smbase + (uint32_t)(ahl * 768 * 4 + arow * 48 + ach * 16);
    const int brow = tid >> 5, bhl = (tid >> 4) & 1, bch = tid & 15;
    const uint32_t* srcB = (bhl ? g_Wp_lo : g_Wp_hi) + (size_t)(h * KP + brow) * FF + f0 + bch * 4;
    const uint32_t dstB = smbase + (uint32_t)(1536 * 4 + bhl * 544 * 4 + brow * 272 + bch * 16);

#define GISSUE(kt) do { const uint32_t bf_ = (uint32_t)(((kt) & 3) * STG_WORDS * 4); \
    CPA16(dstA + bf_, (const float*)(srcA + (kt) * 8)); \
    CPA16(dstB + bf_, (const float*)(srcB + (size_t)(kt) * 8 * FF)); \
    CPCOMMIT(); } while (0)

    // fragment index precompute
    const int wid = tid >> 5, wm = wid >> 2, wn = wid & 3;
    const int lane = tid & 31, gl = lane >> 2, tl = lane & 3;
    int aoff[2][4], boff[2][2];
    #pragma unroll
    for (int mt = 0; mt < 2; mt++) {
        const int r = wm * 32 + mt * 16 + gl;
        aoff[mt][0] = r * 12 + tl;
        aoff[mt][1] = (r + 8) * 12 + tl;
        aoff[mt][2] = r * 12 + tl + 4;
        aoff[mt][3] = (r + 8) * 12 + tl + 4;
    }
    #pragma unroll
    for (int n2 = 0; n2 < 2; n2++) {
        const int fl = wn * 16 + n2 * 8 + gl;
        boff[n2][0] = tl * 68 + fl;
        boff[n2][1] = (tl + 4) * 68 + fl;
    }

    float acc[2][2][4];
    #pragma unroll
    for (int mt = 0; mt < 2; mt++)
        #pragma unroll
        for (int n2 = 0; n2 < 2; n2++)
            #pragma unroll
            for (int i = 0; i < 4; i++) acc[mt][n2][i] = 0.f;

    GISSUE(0); GISSUE(1); GISSUE(2);

    for (int kt = 0; kt < NKT; kt++) {
        if (kt < NKT - 2)       asm volatile("cp.async.wait_group 2;" ::: "memory");
        else if (kt == NKT - 2) asm volatile("cp.async.wait_group 1;" ::: "memory");
        else                    asm volatile("cp.async.wait_group 0;" ::: "memory");
        __syncthreads();
        if (kt + 3 < NKT) GISSUE(kt + 3);

        const uint32_t* bb = smw + (kt & 3) * STG_WORDS;
        const uint32_t* Ah = bb;
        const uint32_t* Al = bb + 768;
        const uint32_t* Bh = bb + 1536;
        const uint32_t* Bl = bb + 2080;
        uint32_t ah[2][4], al[2][4], bh[2][2], bl[2][2];
        #pragma unroll
        for (int mt = 0; mt < 2; mt++)
            #pragma unroll
            for (int i = 0; i < 4; i++) {
                ah[mt][i] = Ah[aoff[mt][i]];
                al[mt][i] = Al[aoff[mt][i]];
            }
        #pragma unroll
        for (int n2 = 0; n2 < 2; n2++)
            #pragma unroll
            for (int i = 0; i < 2; i++) {
                bh[n2][i] = Bh[boff[n2][i]];
                bl[n2][i] = Bl[boff[n2][i]];
            }
        #pragma unroll
        for (int mt = 0; mt < 2; mt++)
            #pragma unroll
            for (int n2 = 0; n2 < 2; n2++) {
                MMA_BF16(acc[mt][n2], ah[mt], bh[n2]);
                MMA_BF16(acc[mt][n2], ah[mt], bl[n2]);
                MMA_BF16(acc[mt][n2], al[mt], bh[n2]);
            }
    }

    // epilogue (+b1 on Q half)
    const size_t hb = (size_t)h * MM * FF;
    #pragma unroll
    for (int mt = 0; mt < 2; mt++) {
        const int mA = m0 + wm * 32 + mt * 16 + gl;
        #pragma unroll
        for (int n2 = 0; n2 < 2; n2++) {
            const int f = f0 + wn * 16 + n2 * 8 + tl * 2;
            float bx = 0.f, by = 0.f;
            if (s == 1) { const float2 bv = *(const float2*)(b1 + f); bx = bv.x; by = bv.y; }
            *(float2*)(g_PQ + hb + (size_t)mA * FF + f) =
                make_float2(acc[mt][n2][0] + bx, acc[mt][n2][1] + by);
            *(float2*)(g_PQ + hb + (size_t)(mA + 8) * FF + f) =
                make_float2(acc[mt][n2][2] + bx, acc[mt][n2][3] + by);
        }
    }
#undef GISSUE
}

// ---------------- writer role: TMA bulk pipeline ----------------
#define JT 10
#define WR_TILES 5120
#define LG_BLOCKS 150
#define SMEM_BYTES 33824

__device__ __forceinline__ void writer_role(
    int wb,
    const float* __restrict__ geo, const float* __restrict__ app, const float* __restrict__ con,
    float* __restrict__ out, int tid, char* sm)
{
    const int b  = wb / 2560;
    const int rem = wb % 2560;
    const int i  = rem / 16;
    const int j0 = (rem % 16) * JT;

    const uint32_t sbase = (uint32_t)__cvta_generic_to_shared(sm);
    const uint32_t mbar  = sbase + 11 * 3072;

    if (tid == 0) {
        asm volatile("mbarrier.init.shared.b64 [%0], 1;" :: "r"(mbar) : "memory");
    }
    __syncthreads();
    if (tid == 0) {
        asm volatile("mbarrier.arrive.expect_tx.shared.b64 _, [%0], %1;"
                     :: "r"(mbar), "r"(11u * 3072u) : "memory");
    }
    __syncthreads();

    if (tid < 33) {
        const int r = tid / 3, seg = tid - 3 * (tid / 3);
        const int n = (r < JT) ? (j0 + r) : i;
        const float* src = ((seg == 0) ? geo : (seg == 1) ? app : con)
                           + ((size_t)b * NN + n) * HH;
        asm volatile(
            "cp.async.bulk.shared::cluster.global.mbarrier::complete_tx::bytes "
            "[%0], [%1], %2, [%3];"
            :: "r"(sbase + (uint32_t)(r * 3072 + seg * 1024)), "l"(src),
               "r"(1024u), "r"(mbar) : "memory");
    }

    if (tid < 2 * JT) {
        asm volatile(
            "{\n\t.reg .pred P;\n"
            "W%=:\n\t"
            "mbarrier.try_wait.parity.shared.b64 P, [%0], 0, 0x989680;\n\t"
            "@!P bra W%=;\n\t}"
            :: "r"(mbar) : "memory");

        const int jj = tid >> 1, half = tid & 1;
        const size_t pidx = (size_t)b * NP + (size_t)i * NN + (j0 + jj);
        float* dst = out + EMB_OFF + pidx * 1536 + half * 768;
        const uint32_t src = sbase + (uint32_t)((half ? JT : jj) * 3072);
        asm volatile(
            "cp.async.bulk.global.shared::cta.bulk_group [%0], [%1], %2;"
            :: "l"(dst), "r"(src), "r"(3072u) : "memory");
        asm volatile("cp.async.bulk.commit_group;" ::: "memory");
        asm volatile("cp.async.bulk.wait_group 0;" ::: "memory");
    }
    __syncthreads();
}

// ---------------- Kernel B: logits (150) + writer (all 5120 tiles) ----------------
__global__ __launch_bounds__(256) void kB_lg_wr(
    const float* __restrict__ geo, const float* __restrict__ app, const float* __restrict__ con,
    float* __restrict__ out,
    const float* __restrict__ W2c, const float* __restrict__ b2c,
    const float* __restrict__ W2r, const float* __restrict__ b2r,
    const float* __restrict__ W2l, const float* __restrict__ b2l)
{
    __shared__ __align__(128) char sm[SMEM_BYTES];
    const int g = blockIdx.x;
    const int tid = threadIdx.x;

    if (g < LG_BLOCKS) {
        float* sP = (float*)sm;            // 32*132
        float* sQ = sP + 32*132;           // 32*128
        float* sW = sQ + 32*128;           // 128
        const int t = g / 50;
        const int r50 = g % 50;
        const int b = r50 / 25;
        const int r25 = r50 % 25;
        const int i0 = (r25 / 5) * 32;
        const int j0 = (r25 % 5) * 32;
        const float* W2 = (t==0 ? W2c : (t==1 ? W2r : W2l));
        const float* b2 = (t==0 ? b2c : (t==1 ? b2r : b2l));
        const size_t boff = (size_t)b * NN * FF;
        const float* Pb = g_PQ + (size_t)(t*2 + 0) * MM * FF + boff;
        const float* Qb = g_PQ + (size_t)(t*2 + 1) * MM * FF + boff;
        const int il = tid >> 5, jl = tid & 31;
        const int lr = tid >> 3, lv = tid & 7;

        float acc[4] = {0.f, 0.f, 0.f, 0.f};
        for (int fc = 0; fc < 4; fc++) {
            const int f0 = fc * 128;
            {
                const size_t ro = (size_t)(j0 + lr) * FF + f0;
                float* dp = sP + lr * 132;
                #pragma unroll
                for (int u = 0; u < 4; u++) {
                    const int fl = (lv + u * 8) * 4;
                    *(float4*)(dp + fl) = *(const float4*)(Pb + ro + fl);
                }
            }
            {
                const size_t ro = (size_t)(i0 + lr) * FF + f0;
                float* dp = sQ + lr * 128;
                #pragma unroll
                for (int u = 0; u < 4; u++) {
                    const int fl = (lv + u * 8) * 4;
                    *(float4*)(dp + fl) = *(const float4*)(Qb + ro + fl);
                }
            }
            if (tid < 128) {
                const float2 w2v = ((const float2*)W2)[f0 + tid];
                sW[tid] = w2v.x - w2v.y;
            }
            __syncthreads();

            const float* pr = sP + jl * 132;
            const float* q0 = sQ + (il * 4) * 128;
            #pragma unroll 4
            for (int f = 0; f < 128; f += 4) {
                const float4 p = *(const float4*)(pr + f);
                const float4 w = *(const float4*)(sW + f);
                #pragma unroll
                for (int a = 0; a < 4; a++) {
                    const float4 q = *(const float4*)(q0 + a * 128 + f);
                    acc[a] = fmaf(fmaxf(p.x + q.x, 0.f), w.x, acc[a]);
                    acc[a] = fmaf(fmaxf(p.y + q.y, 0.f), w.y, acc[a]);
                    acc[a] = fmaf(fmaxf(p.z + q.z, 0.f), w.z, acc[a]);
                    acc[a] = fmaf(fmaxf(p.w + q.w, 0.f), w.w, acc[a]);
                }
            }
            __syncthreads();
        }

        const float bd = b2[0] - b2[1];
        float2* o = (float2*)(out + (size_t)t * LOGIT_ELEMS) + (size_t)b * NP;
        const int j = j0 + jl;
        #pragma unroll
        for (int a = 0; a < 4; a++) {
            const float d = acc[a] + bd;
            const float p0 = 1.0f / (1.0f + __expf(-d));
            o[(size_t)(i0 + il*4 + a) * NN + j] = make_float2(p0, 1.0f - p0);
        }
    } else {
        writer_role(g - LG_BLOCKS, geo, app, con, out, tid, sm);
    }
}

extern "C" void kernel_launch(void* const* d_in, const int* in_sizes, int n_in,
                              void* d_out, int out_size) {
    const float* geo = (const float*)d_in[0];
    const float* app = (const float*)d_in[1];
    const float* con = (const float*)d_in[2];
    const float* W1c = (const float*)d_in[3];
    const float* b1c = (const float*)d_in[4];
    const float* W2c = (const float*)d_in[5];
    const float* b2c = (const float*)d_in[6];
    const float* W1r = (const float*)d_in[7];
    const float* b1r = (const float*)d_in[8];
    const float* W2r = (const float*)d_in[9];
    const float* b2r = (const float*)d_in[10];
    const float* W1l = (const float*)d_in[11];
    const float* b1l = (const float*)d_in[12];
    const float* W2l = (const float*)d_in[13];
    const float* b2l = (const float*)d_in[14];
    float* out = (float*)d_out;

    k_pre<<<PRE_BLOCKS, 256>>>(geo, app, con, W1c, W1r, W1l);
    k_gemm_mma<<<GEMM_BLOCKS, 256>>>(b1c, b1r, b1l);
    kB_lg_wr<<<LG_BLOCKS + WR_TILES, 256>>>(geo, app, con, out,
                                            W2c, b2c, W2r, b2r, W2l, b2l);
}